// round 2
// baseline (speedup 1.0000x reference)
#include <cuda_runtime.h>

#define NB   2
#define NC   256
#define NPIX 4096
#define CI   128
#define EPSV 1e-5f

// ---------------- scratch (device globals; no allocation allowed) ------------
__device__ float g_A [(size_t)NB * NPIX * NPIX];   // affinity logits, 134 MB
__device__ float g_VQ[(size_t)NB * NPIX * CI];     // v(q), pixel-major [n][c]
__device__ float g_VS[(size_t)NB * NPIX * CI];     // v(s)
__device__ float g_KT[(size_t)NB * NPIX * CI];     // k_x^T  [n][c]
__device__ float g_QT[(size_t)NB * NPIX * CI];     // q_x^T  [m][c]
__device__ float g_ST[(size_t)NB * CI * NPIX];     // bn(conv_ts(s)) chan-major
__device__ float g_TQ[(size_t)NB * CI * NPIX];     // bn(conv_tq(q)) chan-major
__device__ float g_rowmax[NB * NPIX];
__device__ float g_rowsum[NB * NPIX];
__device__ float g_colpm [NB * 8 * NPIX];
__device__ float g_colps [NB * 8 * NPIX];
__device__ float g_colmax[NB * NPIX];
__device__ float g_colsum[NB * NPIX];

// conv1x1 destination selector (resolved in device code; avoids symbol-address APIs)
__device__ __forceinline__ float* conv_dst(int dst) {
    switch (dst) {
        case 0: return g_VQ;
        case 1: return g_VS;
        case 2: return g_KT;
        case 3: return g_QT;
        case 4: return g_ST;
        default: return g_TQ;
    }
}

// ---------------- conv1x1 (+optional BN), tiled GEMM W[OC,256] @ X[256,4096] --
template<int OC, bool CHAN_MAJOR>
__global__ __launch_bounds__(256) void conv1x1_kernel(
    const float* __restrict__ X,     // [NB][256][NPIX]
    const float* __restrict__ W,     // [OC][256]
    const float* __restrict__ bias,  // [OC]
    const float* __restrict__ bng, const float* __restrict__ bnb,
    const float* __restrict__ bnm, const float* __restrict__ bnv,
    int dst, int out_off)
{
    const int b  = blockIdx.y;
    const int n0 = blockIdx.x * 128;
    const float* Xb = X + (size_t)b * NC * NPIX;
    float* out = conv_dst(dst);

    __shared__ float Ws[16][OC];
    __shared__ float Xs[16][128];
    constexpr int RPT = OC / 16;   // 8 or 4 rows per thread
    float acc[RPT][8];
    #pragma unroll
    for (int i = 0; i < RPT; i++)
        #pragma unroll
        for (int j = 0; j < 8; j++) acc[i][j] = 0.f;

    const int t  = threadIdx.x;
    const int rg = t >> 4, cg = t & 15;

    for (int k0 = 0; k0 < NC; k0 += 16) {
        for (int i = t; i < OC * 16; i += 256) {
            int oc = i >> 4, kk = i & 15;
            Ws[kk][oc] = W[oc * NC + k0 + kk];
        }
        for (int i = t; i < 16 * 128; i += 256) {
            int kk = i >> 7, px = i & 127;
            Xs[kk][px] = Xb[(size_t)(k0 + kk) * NPIX + n0 + px];
        }
        __syncthreads();
        #pragma unroll
        for (int kk = 0; kk < 16; kk++) {
            float a[RPT], xv[8];
            #pragma unroll
            for (int i = 0; i < RPT; i++) a[i] = Ws[kk][rg * RPT + i];
            #pragma unroll
            for (int j = 0; j < 8; j++) xv[j] = Xs[kk][cg * 8 + j];
            #pragma unroll
            for (int i = 0; i < RPT; i++)
                #pragma unroll
                for (int j = 0; j < 8; j++) acc[i][j] += a[i] * xv[j];
        }
        __syncthreads();
    }

    #pragma unroll
    for (int i = 0; i < RPT; i++) {
        int oc = rg * RPT + i;
        float sc = 1.f, off = bias[oc];
        if (CHAN_MAJOR) {                      // fused BN
            float inv = bng[oc] * rsqrtf(bnv[oc] + EPSV);
            sc  = inv;
            off = (bias[oc] - bnm[oc]) * inv + bnb[oc];
        }
        #pragma unroll
        for (int j = 0; j < 8; j++) {
            int px = cg * 8 + j;
            float v = acc[i][j] * sc + off;
            if (CHAN_MAJOR)
                out[((size_t)b * CI + oc) * NPIX + n0 + px] = v;
            else
                out[((size_t)b * NPIX + n0 + px) * CI + out_off + oc] = v;
        }
    }
}

// ---------------- A[n][m] = dot(KT[n], QT[m])  (NT GEMM, K=128) --------------
__global__ __launch_bounds__(256) void gemmA_kernel()
{
    const int b  = blockIdx.z;
    const int m0 = blockIdx.x * 128;
    const int n0 = blockIdx.y * 128;
    const float* Kp = g_KT + (size_t)b * NPIX * CI;
    const float* Qp = g_QT + (size_t)b * NPIX * CI;

    __shared__ float Ks[16][132];
    __shared__ float Qs[16][132];
    float acc[8][8] = {};
    const int t  = threadIdx.x;
    const int rg = t >> 4, cg = t & 15;

    for (int k0 = 0; k0 < CI; k0 += 16) {
        for (int i = t; i < 128 * 16; i += 256) {
            int row = i >> 4, kk = i & 15;
            Ks[kk][row] = Kp[(size_t)(n0 + row) * CI + k0 + kk];
            Qs[kk][row] = Qp[(size_t)(m0 + row) * CI + k0 + kk];
        }
        __syncthreads();
        #pragma unroll
        for (int kk = 0; kk < 16; kk++) {
            float a[8], q[8];
            #pragma unroll
            for (int i = 0; i < 8; i++) a[i] = Ks[kk][rg * 8 + i];
            #pragma unroll
            for (int j = 0; j < 8; j++) q[j] = Qs[kk][cg * 8 + j];
            #pragma unroll
            for (int i = 0; i < 8; i++)
                #pragma unroll
                for (int j = 0; j < 8; j++) acc[i][j] += a[i] * q[j];
        }
        __syncthreads();
    }
    float* Ab = g_A + (size_t)b * NPIX * NPIX;
    #pragma unroll
    for (int i = 0; i < 8; i++)
        #pragma unroll
        for (int j = 0; j < 8; j++)
            Ab[(size_t)(n0 + rg * 8 + i) * NPIX + m0 + cg * 8 + j] = acc[i][j];
}

// ---------------- softmax stats (online max/sum) -----------------------------
__global__ __launch_bounds__(256) void rowstats_kernel()
{
    const int b = blockIdx.y, n = blockIdx.x, t = threadIdx.x;
    const float* row = g_A + ((size_t)b * NPIX + n) * NPIX;
    float m = -1e30f, s = 0.f;
    for (int j = t; j < NPIX; j += 256) {
        float x = row[j];
        if (x > m) { s *= __expf(m - x); m = x; }
        s += __expf(x - m);
    }
    __shared__ float sm_[256], ss_[256];
    sm_[t] = m; ss_[t] = s;
    __syncthreads();
    for (int st = 128; st > 0; st >>= 1) {
        if (t < st) {
            float m2 = sm_[t + st], s2 = ss_[t + st];
            float M = fmaxf(sm_[t], m2);
            ss_[t] = ss_[t] * __expf(sm_[t] - M) + s2 * __expf(m2 - M);
            sm_[t] = M;
        }
        __syncthreads();
    }
    if (t == 0) { g_rowmax[b * NPIX + n] = sm_[0]; g_rowsum[b * NPIX + n] = ss_[0]; }
}

__global__ __launch_bounds__(256) void colstats_partial_kernel()
{
    const int b   = blockIdx.z;
    const int col = blockIdx.x * 256 + threadIdx.x;
    const int nc  = blockIdx.y;     // 0..7, 512 rows each
    const float* Ab = g_A + (size_t)b * NPIX * NPIX;
    float m = -1e30f, s = 0.f;
    const int nend = nc * 512 + 512;
    for (int n = nc * 512; n < nend; n++) {
        float x = Ab[(size_t)n * NPIX + col];
        if (x > m) { s *= __expf(m - x); m = x; }
        s += __expf(x - m);
    }
    g_colpm[((size_t)b * 8 + nc) * NPIX + col] = m;
    g_colps[((size_t)b * 8 + nc) * NPIX + col] = s;
}

__global__ __launch_bounds__(256) void colstats_combine_kernel()
{
    int idx = blockIdx.x * 256 + threadIdx.x;     // over NB*NPIX
    int b = idx / NPIX, col = idx % NPIX;
    float m = -1e30f, s = 0.f;
    for (int c = 0; c < 8; c++) {
        float m2 = g_colpm[((size_t)b * 8 + c) * NPIX + col];
        float s2 = g_colps[((size_t)b * 8 + c) * NPIX + col];
        float M = fmaxf(m, m2);
        s = s * __expf(m - M) + s2 * __expf(m2 - M);
        m = M;
    }
    g_colmax[idx] = m; g_colsum[idx] = s;
}

// ---------------- PV GEMM: E = scale * softmax(A) @ V / sum + T --------------
// mode 0: E_s (row softmax, V=v_s, T=s_t); mode 1: E_q (col softmax via A^T, V=v_q, T=q_t)
__global__ __launch_bounds__(256) void pv_kernel(
    const float* __restrict__ scale_p,
    float* __restrict__ out_eq, float* __restrict__ out_es)
{
    const int mode = blockIdx.z;
    const int b    = blockIdx.y;
    const int r0   = blockIdx.x * 128;
    const float* Ab = g_A + (size_t)b * NPIX * NPIX;
    const float* V  = (mode ? g_VQ : g_VS) + (size_t)b * NPIX * CI;
    const float* mx = (mode ? g_colmax : g_rowmax) + b * NPIX;
    const float* sm = (mode ? g_colsum : g_rowsum) + b * NPIX;
    const float* T  = (mode ? g_TQ : g_ST) + (size_t)b * CI * NPIX;
    float* out = (mode ? out_eq : out_es) + (size_t)b * CI * NPIX;
    const float scale = scale_p[0];

    __shared__ float As[16][132];
    __shared__ float Vs[16][132];
    __shared__ float rmx[128];
    const int t = threadIdx.x;
    if (t < 128) rmx[t] = mx[r0 + t];
    __syncthreads();

    float acc[8][8] = {};
    const int rg = t >> 4, cg = t & 15;

    for (int k0 = 0; k0 < NPIX; k0 += 16) {
        if (mode == 0) {
            for (int i = t; i < 128 * 16; i += 256) {
                int row = i >> 4, kk = i & 15;
                As[kk][row] = __expf(Ab[(size_t)(r0 + row) * NPIX + k0 + kk] - rmx[row]);
            }
        } else {
            for (int i = t; i < 128 * 16; i += 256) {
                int row = i & 127, kk = i >> 7;
                As[kk][row] = __expf(Ab[(size_t)(k0 + kk) * NPIX + r0 + row] - rmx[row]);
            }
        }
        for (int i = t; i < 16 * 128; i += 256) {
            int kk = i >> 7, c = i & 127;
            Vs[kk][c] = V[(size_t)(k0 + kk) * CI + c];
        }
        __syncthreads();
        #pragma unroll
        for (int kk = 0; kk < 16; kk++) {
            float a[8], v[8];
            #pragma unroll
            for (int i = 0; i < 8; i++) a[i] = As[kk][rg * 8 + i];
            #pragma unroll
            for (int j = 0; j < 8; j++) v[j] = Vs[kk][cg * 8 + j];
            #pragma unroll
            for (int i = 0; i < 8; i++)
                #pragma unroll
                for (int j = 0; j < 8; j++) acc[i][j] += a[i] * v[j];
        }
        __syncthreads();
    }

    #pragma unroll
    for (int i = 0; i < 8; i++) {
        int r = r0 + rg * 8 + i;
        float invs = scale / sm[r];
        #pragma unroll
        for (int j = 0; j < 8; j++) {
            int c = cg * 8 + j;
            out[(size_t)c * NPIX + r] = acc[i][j] * invs + T[(size_t)c * NPIX + r];
        }
    }
}

// ---------------- 3x3 conv (SAME) + BN + ReLU on cat(E_q, E_s) ---------------
__global__ __launch_bounds__(256) void conv3x3_kernel(
    const float* __restrict__ Wc,   // [128][256][3][3]
    const float* __restrict__ bng, const float* __restrict__ bnb,
    const float* __restrict__ bnm, const float* __restrict__ bnv,
    const float* __restrict__ Eq, const float* __restrict__ Es,
    float* __restrict__ outp)
{
    const int b = blockIdx.y;
    const int y = blockIdx.x;
    __shared__ float Xs[8][3][68];        // 8 ic, rows y-1..y+1, 66 cols (halo)
    __shared__ float Wsm[8][9][128];      // [ic][tap][oc]
    const int t   = threadIdx.x;
    const int pxg = t & 15, ocg = t >> 4;
    float acc[8][4] = {};

    for (int ic0 = 0; ic0 < 256; ic0 += 8) {
        const float* src = (ic0 < 128)
            ? Eq + ((size_t)b * CI + ic0) * NPIX
            : Es + ((size_t)b * CI + (ic0 - 128)) * NPIX;

        for (int i = t; i < 8 * 3 * 66; i += 256) {
            int ic = i / 198, rem = i - ic * 198;
            int dy = rem / 66, xx = rem - dy * 66;
            int xg = xx - 1, yg = y + dy - 1;
            float v = 0.f;
            if (xg >= 0 && xg < 64 && yg >= 0 && yg < 64)
                v = src[(size_t)ic * NPIX + yg * 64 + xg];
            Xs[ic][dy][xx] = v;
        }
        {
            int oc = t >> 1, half = t & 1;
            const float* wp = Wc + (size_t)oc * 2304 + (ic0 + half * 4) * 9;
            #pragma unroll
            for (int j = 0; j < 36; j++) {
                int icl = half * 4 + j / 9, tap = j - (j / 9) * 9;
                Wsm[icl][tap][oc] = wp[j];
            }
        }
        __syncthreads();

        #pragma unroll
        for (int ic = 0; ic < 8; ic++) {
            #pragma unroll
            for (int tap = 0; tap < 9; tap++) {
                const int dy = tap / 3, dx = tap - (tap / 3) * 3;
                float w[8], xv[4];
                #pragma unroll
                for (int o = 0; o < 8; o++) w[o] = Wsm[ic][tap][ocg * 8 + o];
                #pragma unroll
                for (int p = 0; p < 4; p++) xv[p] = Xs[ic][dy][pxg * 4 + p + dx];
                #pragma unroll
                for (int o = 0; o < 8; o++)
                    #pragma unroll
                    for (int p = 0; p < 4; p++) acc[o][p] += w[o] * xv[p];
            }
        }
        __syncthreads();
    }

    #pragma unroll
    for (int o = 0; o < 8; o++) {
        int oc = ocg * 8 + o;
        float inv = bng[oc] * rsqrtf(bnv[oc] + EPSV);
        float off = bnb[oc] - bnm[oc] * inv;
        #pragma unroll
        for (int p = 0; p < 4; p++) {
            int px = pxg * 4 + p;
            float v = acc[o][p] * inv + off;
            outp[((size_t)b * CI + oc) * NPIX + y * 64 + px] = fmaxf(v, 0.f);
        }
    }
}

// ---------------- launch ------------------------------------------------------
extern "C" void kernel_launch(void* const* d_in, const int* in_sizes, int n_in,
                              void* d_out, int out_size)
{
    (void)in_sizes; (void)n_in; (void)out_size;
    const float* q     = (const float*)d_in[0];
    const float* s     = (const float*)d_in[1];
    const float* scale = (const float*)d_in[2];
    const float* w_v   = (const float*)d_in[3];  const float* b_v  = (const float*)d_in[4];
    const float* w_k1  = (const float*)d_in[5];  const float* b_k1 = (const float*)d_in[6];
    const float* w_q1  = (const float*)d_in[7];  const float* b_q1 = (const float*)d_in[8];
    const float* w_k2  = (const float*)d_in[9];  const float* b_k2 = (const float*)d_in[10];
    const float* w_q2  = (const float*)d_in[11]; const float* b_q2 = (const float*)d_in[12];
    const float* w_ts  = (const float*)d_in[13]; const float* b_ts = (const float*)d_in[14];
    const float* gts   = (const float*)d_in[15]; const float* bets = (const float*)d_in[16];
    const float* mts   = (const float*)d_in[17]; const float* vts  = (const float*)d_in[18];
    const float* w_tq  = (const float*)d_in[19]; const float* b_tq = (const float*)d_in[20];
    const float* gtq   = (const float*)d_in[21]; const float* betq = (const float*)d_in[22];
    const float* mtq   = (const float*)d_in[23]; const float* vtq  = (const float*)d_in[24];
    const float* w_cat = (const float*)d_in[25];
    const float* gcat  = (const float*)d_in[26]; const float* becat= (const float*)d_in[27];
    const float* mcat  = (const float*)d_in[28]; const float* vcat = (const float*)d_in[29];

    float* out  = (float*)d_out;
    float* cpam = out;                                   // [2,128,64,64]
    float* Eq   = out + (size_t)NB * CI * NPIX;          // [2,128,64,64]
    float* Es   = out + 2 * (size_t)NB * CI * NPIX;      // [2,128,64,64]

    dim3 g32(32, NB);
    // values / keys / queries / transform branches
    conv1x1_kernel<128, false><<<g32, 256>>>(q, w_v,  b_v,  nullptr, nullptr, nullptr, nullptr, 0, 0);
    conv1x1_kernel<128, false><<<g32, 256>>>(s, w_v,  b_v,  nullptr, nullptr, nullptr, nullptr, 1, 0);
    conv1x1_kernel< 64, false><<<g32, 256>>>(q, w_k1, b_k1, nullptr, nullptr, nullptr, nullptr, 2, 0);
    conv1x1_kernel< 64, false><<<g32, 256>>>(s, w_k2, b_k2, nullptr, nullptr, nullptr, nullptr, 2, 64);
    conv1x1_kernel< 64, false><<<g32, 256>>>(q, w_q1, b_q1, nullptr, nullptr, nullptr, nullptr, 3, 0);
    conv1x1_kernel< 64, false><<<g32, 256>>>(s, w_q2, b_q2, nullptr, nullptr, nullptr, nullptr, 3, 64);
    conv1x1_kernel<128, true ><<<g32, 256>>>(s, w_ts, b_ts, gts, bets, mts, vts, 4, 0);
    conv1x1_kernel<128, true ><<<g32, 256>>>(q, w_tq, b_tq, gtq, betq, mtq, vtq, 5, 0);

    gemmA_kernel<<<dim3(32, 32, NB), 256>>>();

    rowstats_kernel<<<dim3(NPIX, NB), 256>>>();
    colstats_partial_kernel<<<dim3(16, 8, NB), 256>>>();
    colstats_combine_kernel<<<(NB * NPIX) / 256, 256>>>();

    pv_kernel<<<dim3(32, NB, 2), 256>>>(scale, Eq, Es);

    conv3x3_kernel<<<dim3(64, NB), 256>>>(w_cat, gcat, becat, mcat, vcat, Eq, Es, cpam);
}

// round 4
// speedup vs baseline: 2.1638x; 2.1638x over previous
#include <cuda_runtime.h>
#include <cuda_bf16.h>
#include <cstdint>

#define NB   2
#define NC   256
#define NPIX 4096
#define CI   128
#define EPSV 1e-5f

__device__ float g_E  [(size_t)NB * NPIX * NPIX];
__device__ float g_ET [(size_t)NB * NPIX * NPIX];
__device__ float g_VTQ[(size_t)NB * CI * NPIX];
__device__ float g_VTS[(size_t)NB * CI * NPIX];
__device__ float g_KT [(size_t)NB * NPIX * CI];
__device__ float g_QT [(size_t)NB * NPIX * CI];
__device__ float g_ST [(size_t)NB * CI * NPIX];
__device__ float g_TQ [(size_t)NB * CI * NPIX];
__device__ float g_rowsum[NB * NPIX];
__device__ float g_colsum[NB * NPIX];

// byte offsets into dynamic smem (74240 B)
#define OFF_AH 0
#define OFF_AL 18432
#define OFF_BH 36864
#define OFF_BL 55296
#define OFF_RS 73728
#define SMEMSZ 74240

__device__ __forceinline__ uint32_t f2tf(float v) {
    uint32_t r;
    asm("cvt.rna.tf32.f32 %0, %1;" : "=r"(r) : "f"(v));
    return r;
}
__device__ __forceinline__ void mma_tf32(float* c, const uint32_t* a, uint32_t b0, uint32_t b1) {
    asm("mma.sync.aligned.m16n8k8.row.col.f32.tf32.tf32.f32 "
        "{%0,%1,%2,%3},{%4,%5,%6,%7},{%8,%9},{%0,%1,%2,%3};"
        : "+f"(c[0]), "+f"(c[1]), "+f"(c[2]), "+f"(c[3])
        : "r"(a[0]), "r"(a[1]), "r"(a[2]), "r"(a[3]), "r"(b0), "r"(b1));
}
__device__ __forceinline__ void mma_bf16(float* c, const uint32_t* a, uint32_t b0, uint32_t b1) {
    asm("mma.sync.aligned.m16n8k16.row.col.f32.bf16.bf16.f32 "
        "{%0,%1,%2,%3},{%4,%5,%6,%7},{%8,%9},{%0,%1,%2,%3};"
        : "+f"(c[0]), "+f"(c[1]), "+f"(c[2]), "+f"(c[3])
        : "r"(a[0]), "r"(a[1]), "r"(a[2]), "r"(a[3]), "r"(b0), "r"(b1));
}

// ---------------- zero sums ----------------
__global__ void zero_sums() {
    int i = blockIdx.x * 256 + threadIdx.x;
    if (i < NB * NPIX) { g_rowsum[i] = 0.f; g_colsum[i] = 0.f; }
}

// ============ gemmA: E = exp(KT . QT^T) via tf32x2 mma, fused sums ===========
__global__ __launch_bounds__(256, 1) void gemmA_mma()
{
    extern __shared__ char sm[];
    uint32_t* Ah = (uint32_t*)(sm + OFF_AH);   // [128][36] tf32
    uint32_t* Al = (uint32_t*)(sm + OFF_AL);
    uint32_t* Bh = (uint32_t*)(sm + OFF_BH);
    uint32_t* Bl = (uint32_t*)(sm + OFF_BL);
    const int t = threadIdx.x, lane = t & 31, wid = t >> 5;
    const int g = lane >> 2, tg = lane & 3;
    const int b = blockIdx.z, n0 = blockIdx.x * 128, m0 = blockIdx.y * 128;
    const int wr = (wid & 3) * 32, wc = (wid >> 2) * 64;
    const float* Ap = g_KT + (size_t)b * NPIX * CI + (size_t)n0 * CI;
    const float* Bp = g_QT + (size_t)b * NPIX * CI + (size_t)m0 * CI;
    float c[2][8][4] = {};

    for (int kc = 0; kc < 4; kc++) {
        #pragma unroll
        for (int p = 0; p < 4; p++) {
            int idx = t + p * 256;
            int row = idx >> 3, seg = idx & 7;
            float4 va = *(const float4*)(Ap + (size_t)row * CI + kc * 32 + seg * 4);
            float4 vb = *(const float4*)(Bp + (size_t)row * CI + kc * 32 + seg * 4);
            uint4 h, l;
            h.x = f2tf(va.x); l.x = f2tf(va.x - __uint_as_float(h.x));
            h.y = f2tf(va.y); l.y = f2tf(va.y - __uint_as_float(h.y));
            h.z = f2tf(va.z); l.z = f2tf(va.z - __uint_as_float(h.z));
            h.w = f2tf(va.w); l.w = f2tf(va.w - __uint_as_float(h.w));
            *(uint4*)(Ah + row * 36 + seg * 4) = h;
            *(uint4*)(Al + row * 36 + seg * 4) = l;
            h.x = f2tf(vb.x); l.x = f2tf(vb.x - __uint_as_float(h.x));
            h.y = f2tf(vb.y); l.y = f2tf(vb.y - __uint_as_float(h.y));
            h.z = f2tf(vb.z); l.z = f2tf(vb.z - __uint_as_float(h.z));
            h.w = f2tf(vb.w); l.w = f2tf(vb.w - __uint_as_float(h.w));
            *(uint4*)(Bh + row * 36 + seg * 4) = h;
            *(uint4*)(Bl + row * 36 + seg * 4) = l;
        }
        __syncthreads();
        #pragma unroll
        for (int k0 = 0; k0 < 32; k0 += 8) {
            uint32_t ah[2][4], al[2][4];
            #pragma unroll
            for (int mt = 0; mt < 2; mt++) {
                int base = (wr + mt * 16 + g) * 36 + k0 + tg;
                ah[mt][0] = Ah[base];       ah[mt][1] = Ah[base + 288];
                ah[mt][2] = Ah[base + 4];   ah[mt][3] = Ah[base + 292];
                al[mt][0] = Al[base];       al[mt][1] = Al[base + 288];
                al[mt][2] = Al[base + 4];   al[mt][3] = Al[base + 292];
            }
            #pragma unroll
            for (int nt = 0; nt < 8; nt++) {
                int bb = (wc + nt * 8 + g) * 36 + k0 + tg;
                uint32_t bh0 = Bh[bb], bh1 = Bh[bb + 4];
                uint32_t bl0 = Bl[bb], bl1 = Bl[bb + 4];
                #pragma unroll
                for (int mt = 0; mt < 2; mt++) {
                    mma_tf32(c[mt][nt], ah[mt], bh0, bh1);
                    mma_tf32(c[mt][nt], al[mt], bh0, bh1);
                    mma_tf32(c[mt][nt], ah[mt], bl0, bl1);
                }
            }
        }
        __syncthreads();
    }

    float* Tb = (float*)sm;    // [128][132]
    #pragma unroll
    for (int mt = 0; mt < 2; mt++)
        #pragma unroll
        for (int nt = 0; nt < 8; nt++)
            #pragma unroll
            for (int i = 0; i < 4; i++) {
                int row = wr + mt * 16 + g + (i >> 1) * 8;
                int col = wc + nt * 8 + tg * 2 + (i & 1);
                Tb[row * 132 + col] = __expf(c[mt][nt][i]);
            }
    __syncthreads();

    float* Eb  = g_E  + (size_t)b * NPIX * NPIX;
    float* ETb = g_ET + (size_t)b * NPIX * NPIX;
    for (int i = t; i < 16384; i += 256) {
        int r = i >> 7, cl = i & 127;
        Eb[(size_t)(n0 + r) * NPIX + m0 + cl] = Tb[r * 132 + cl];
    }
    for (int i = t; i < 16384; i += 256) {
        int cl = i >> 7, r = i & 127;
        ETb[(size_t)(m0 + cl) * NPIX + n0 + r] = Tb[r * 132 + cl];
    }
    if (t < 128) {
        float s = 0.f;
        #pragma unroll 8
        for (int j = 0; j < 128; j++) s += Tb[t * 132 + j];
        atomicAdd(g_rowsum + b * NPIX + n0 + t, s);
    } else {
        int cl = t - 128;
        float s = 0.f;
        #pragma unroll 8
        for (int j = 0; j < 128; j++) s += Tb[j * 132 + cl];
        atomicAdd(g_colsum + b * NPIX + m0 + cl, s);
    }
}

// ============ pv: out[c][r] = scale*(E . VT^T)/sum + T via bf16x3 ============
__global__ __launch_bounds__(256, 1) void pv_mma(const float* __restrict__ scale_p,
                                                 float* __restrict__ outEq,
                                                 float* __restrict__ outEs)
{
    extern __shared__ char sm[];
    const int t = threadIdx.x, lane = t & 31, wid = t >> 5;
    const int g = lane >> 2, tg = lane & 3;
    const int r0 = blockIdx.x * 128, b = blockIdx.y, mode = blockIdx.z;
    const int wr = (wid & 3) * 32, wc = (wid >> 2) * 64;
    const float* Ap = (mode ? g_ET : g_E) + (size_t)b * NPIX * NPIX + (size_t)r0 * NPIX;
    const float* Bp = (mode ? g_VTQ : g_VTS) + (size_t)b * CI * NPIX;
    const float* sums = (mode ? g_colsum : g_rowsum) + (size_t)b * NPIX + r0;
    const float* T = (mode ? g_TQ : g_ST) + (size_t)b * CI * NPIX;
    float* outp = (mode ? outEq : outEs) + (size_t)b * CI * NPIX;
    float* RS = (float*)(sm + OFF_RS);
    if (t < 128) RS[t] = scale_p[0] / sums[t];

    float c[2][8][4] = {};
    for (int kc = 0; kc < 64; kc++) {
        #pragma unroll
        for (int p = 0; p < 8; p++) {
            int idx = t + p * 256;
            int row = idx >> 4, seg = idx & 15;
            float4 va = *(const float4*)(Ap + (size_t)row * NPIX + kc * 64 + seg * 4);
            float4 vb = *(const float4*)(Bp + (size_t)row * NPIX + kc * 64 + seg * 4);
            uint32_t boff = row * 144 + seg * 8;
            __nv_bfloat16 h0, h1, h2, h3;
            uint2 hp, lp;
            h0 = __float2bfloat16(va.x); h1 = __float2bfloat16(va.y);
            h2 = __float2bfloat16(va.z); h3 = __float2bfloat16(va.w);
            hp.x = (uint32_t)__bfloat16_as_ushort(h0) | ((uint32_t)__bfloat16_as_ushort(h1) << 16);
            hp.y = (uint32_t)__bfloat16_as_ushort(h2) | ((uint32_t)__bfloat16_as_ushort(h3) << 16);
            lp.x = (uint32_t)__bfloat16_as_ushort(__float2bfloat16(va.x - __bfloat162float(h0)))
                 | ((uint32_t)__bfloat16_as_ushort(__float2bfloat16(va.y - __bfloat162float(h1))) << 16);
            lp.y = (uint32_t)__bfloat16_as_ushort(__float2bfloat16(va.z - __bfloat162float(h2)))
                 | ((uint32_t)__bfloat16_as_ushort(__float2bfloat16(va.w - __bfloat162float(h3))) << 16);
            *(uint2*)(sm + OFF_AH + boff) = hp;
            *(uint2*)(sm + OFF_AL + boff) = lp;
            h0 = __float2bfloat16(vb.x); h1 = __float2bfloat16(vb.y);
            h2 = __float2bfloat16(vb.z); h3 = __float2bfloat16(vb.w);
            hp.x = (uint32_t)__bfloat16_as_ushort(h0) | ((uint32_t)__bfloat16_as_ushort(h1) << 16);
            hp.y = (uint32_t)__bfloat16_as_ushort(h2) | ((uint32_t)__bfloat16_as_ushort(h3) << 16);
            lp.x = (uint32_t)__bfloat16_as_ushort(__float2bfloat16(vb.x - __bfloat162float(h0)))
                 | ((uint32_t)__bfloat16_as_ushort(__float2bfloat16(vb.y - __bfloat162float(h1))) << 16);
            lp.y = (uint32_t)__bfloat16_as_ushort(__float2bfloat16(vb.z - __bfloat162float(h2)))
                 | ((uint32_t)__bfloat16_as_ushort(__float2bfloat16(vb.w - __bfloat162float(h3))) << 16);
            *(uint2*)(sm + OFF_BH + boff) = hp;
            *(uint2*)(sm + OFF_BL + boff) = lp;
        }
        __syncthreads();
        #pragma unroll
        for (int k0 = 0; k0 < 64; k0 += 16) {
            uint32_t ah[2][4], al[2][4];
            #pragma unroll
            for (int mt = 0; mt < 2; mt++) {
                uint32_t base = (wr + mt * 16 + g) * 144 + (k0 + tg * 2) * 2;
                ah[mt][0] = *(uint32_t*)(sm + OFF_AH + base);
                ah[mt][1] = *(uint32_t*)(sm + OFF_AH + base + 1152);
                ah[mt][2] = *(uint32_t*)(sm + OFF_AH + base + 16);
                ah[mt][3] = *(uint32_t*)(sm + OFF_AH + base + 1168);
                al[mt][0] = *(uint32_t*)(sm + OFF_AL + base);
                al[mt][1] = *(uint32_t*)(sm + OFF_AL + base + 1152);
                al[mt][2] = *(uint32_t*)(sm + OFF_AL + base + 16);
                al[mt][3] = *(uint32_t*)(sm + OFF_AL + base + 1168);
            }
            #pragma unroll
            for (int nt = 0; nt < 8; nt++) {
                uint32_t bb = (wc + nt * 8 + g) * 144 + (k0 + tg * 2) * 2;
                uint32_t bh0 = *(uint32_t*)(sm + OFF_BH + bb);
                uint32_t bh1 = *(uint32_t*)(sm + OFF_BH + bb + 16);
                uint32_t bl0 = *(uint32_t*)(sm + OFF_BL + bb);
                uint32_t bl1 = *(uint32_t*)(sm + OFF_BL + bb + 16);
                #pragma unroll
                for (int mt = 0; mt < 2; mt++) {
                    mma_bf16(c[mt][nt], ah[mt], bh0, bh1);
                    mma_bf16(c[mt][nt], al[mt], bh0, bh1);
                    mma_bf16(c[mt][nt], ah[mt], bl0, bl1);
                }
            }
        }
        __syncthreads();
    }

    float* Tb = (float*)sm;   // [128][132]
    #pragma unroll
    for (int mt = 0; mt < 2; mt++)
        #pragma unroll
        for (int nt = 0; nt < 8; nt++)
            #pragma unroll
            for (int i = 0; i < 4; i++) {
                int row = wr + mt * 16 + g + (i >> 1) * 8;
                int col = wc + nt * 8 + tg * 2 + (i & 1);
                Tb[row * 132 + col] = c[mt][nt][i] * RS[row];
            }
    __syncthreads();
    for (int i = t; i < 16384; i += 256) {
        int cl = i >> 7, r = i & 127;
        size_t gi = (size_t)cl * NPIX + r0 + r;
        outp[gi] = Tb[r * 132 + cl] + T[gi];
    }
}

// ---------------- fused conv1x1: 12 jobs ----------------
__global__ __launch_bounds__(256) void convs_kernel(
    const float* __restrict__ q, const float* __restrict__ s,
    const float* __restrict__ w_v,  const float* __restrict__ b_v,
    const float* __restrict__ w_k1, const float* __restrict__ b_k1,
    const float* __restrict__ w_q1, const float* __restrict__ b_q1,
    const float* __restrict__ w_k2, const float* __restrict__ b_k2,
    const float* __restrict__ w_q2, const float* __restrict__ b_q2,
    const float* __restrict__ w_ts, const float* __restrict__ b_ts,
    const float* __restrict__ gts,  const float* __restrict__ bets,
    const float* __restrict__ mts,  const float* __restrict__ vts,
    const float* __restrict__ w_tq, const float* __restrict__ b_tq,
    const float* __restrict__ gtq,  const float* __restrict__ betq,
    const float* __restrict__ mtq,  const float* __restrict__ vtq)
{
    const int j = blockIdx.z, b = blockIdx.y, n0 = blockIdx.x * 128;
    const float *X, *W, *Bi, *bg = nullptr, *bb = nullptr, *bm = nullptr, *bv = nullptr;
    float* dst; int ocb = 0, co = 0; bool chanmaj = true, hasbn = false;
    switch (j) {
        case 0:  X = q; W = w_v;  Bi = b_v;  dst = g_VTQ; ocb = 0;  co = 0;  break;
        case 1:  X = q; W = w_v;  Bi = b_v;  dst = g_VTQ; ocb = 64; co = 64; break;
        case 2:  X = s; W = w_v;  Bi = b_v;  dst = g_VTS; ocb = 0;  co = 0;  break;
        case 3:  X = s; W = w_v;  Bi = b_v;  dst = g_VTS; ocb = 64; co = 64; break;
        case 4:  X = q; W = w_k1; Bi = b_k1; dst = g_KT;  chanmaj = false; co = 0;  break;
        case 5:  X = s; W = w_k2; Bi = b_k2; dst = g_KT;  chanmaj = false; co = 64; break;
        case 6:  X = q; W = w_q1; Bi = b_q1; dst = g_QT;  chanmaj = false; co = 0;  break;
        case 7:  X = s; W = w_q2; Bi = b_q2; dst = g_QT;  chanmaj = false; co = 64; break;
        case 8:  X = s; W = w_ts; Bi = b_ts; dst = g_ST;  ocb = 0;  co = 0;  hasbn = true; bg = gts; bb = bets; bm = mts; bv = vts; break;
        case 9:  X = s; W = w_ts; Bi = b_ts; dst = g_ST;  ocb = 64; co = 64; hasbn = true; bg = gts; bb = bets; bm = mts; bv = vts; break;
        case 10: X = q; W = w_tq; Bi = b_tq; dst = g_TQ;  ocb = 0;  co = 0;  hasbn = true; bg = gtq; bb = betq; bm = mtq; bv = vtq; break;
        default: X = q; W = w_tq; Bi = b_tq; dst = g_TQ;  ocb = 64; co = 64; hasbn = true; bg = gtq; bb = betq; bm = mtq; bv = vtq; break;
    }
    const float* Xb = X + (size_t)b * NC * NPIX;
    __shared__ float Ws[16][64];
    __shared__ float Xs[16][128];
    float acc[4][8] = {};
    const int t = threadIdx.x, rg = t >> 4, cg = t & 15;

    for (int k0 = 0; k0 < NC; k0 += 16) {
        for (int i = t; i < 1024; i += 256) {
            int oc = i >> 4, kk = i & 15;
            Ws[kk][oc] = W[(ocb + oc) * NC + k0 + kk];
        }
        for (int i = t; i < 2048; i += 256) {
            int kk = i >> 7, px = i & 127;
            Xs[kk][px] = Xb[(size_t)(k0 + kk) * NPIX + n0 + px];
        }
        __syncthreads();
        #pragma unroll
        for (int kk = 0; kk < 16; kk++) {
            float a[4], xv[8];
            #pragma unroll
            for (int i = 0; i < 4; i++) a[i] = Ws[kk][rg * 4 + i];
            #pragma unroll
            for (int jx = 0; jx < 8; jx++) xv[jx] = Xs[kk][cg * 8 + jx];
            #pragma unroll
            for (int i = 0; i < 4; i++)
                #pragma unroll
                for (int jx = 0; jx < 8; jx++) acc[i][jx] += a[i] * xv[jx];
        }
        __syncthreads();
    }
    #pragma unroll
    for (int i = 0; i < 4; i++) {
        int oc = rg * 4 + i, gi = ocb + oc;
        float sc = 1.f, off = Bi[gi];
        if (hasbn) {
            float inv = bg[gi] * rsqrtf(bv[gi] + EPSV);
            sc = inv; off = (Bi[gi] - bm[gi]) * inv + bb[gi];
        }
        #pragma unroll
        for (int jx = 0; jx < 8; jx++) {
            int px = cg * 8 + jx;
            float v = acc[i][jx] * sc + off;
            if (chanmaj) dst[((size_t)b * CI + co + oc) * NPIX + n0 + px] = v;
            else         dst[((size_t)b * NPIX + n0 + px) * CI + co + oc] = v;
        }
    }
}

// ---------------- 3x3 conv + BN + ReLU ----------------
__global__ __launch_bounds__(256) void conv3x3_kernel(
    const float* __restrict__ Wc,
    const float* __restrict__ bng, const float* __restrict__ bnb,
    const float* __restrict__ bnm, const float* __restrict__ bnv,
    const float* __restrict__ Eq, const float* __restrict__ Es,
    float* __restrict__ outp)
{
    const int b = blockIdx.y, y = blockIdx.x, zh = blockIdx.z;
    __shared__ float Xs[8][3][68];
    __shared__ float Wsm[8][9][64];
    const int t = threadIdx.x, pxg = t & 15, ocg = t >> 4;
    float acc[4][4] = {};

    for (int ic0 = 0; ic0 < 256; ic0 += 8) {
        const float* src = (ic0 < 128)
            ? Eq + ((size_t)b * CI + ic0) * NPIX
            : Es + ((size_t)b * CI + (ic0 - 128)) * NPIX;
        for (int i = t; i < 1584; i += 256) {
            int ic = i / 198, rem = i - ic * 198;
            int dy = rem / 66, xx = rem - dy * 66;
            int xg = xx - 1, yg = y + dy - 1;
            float v = 0.f;
            if (xg >= 0 && xg < 64 && yg >= 0 && yg < 64)
                v = src[(size_t)ic * NPIX + yg * 64 + xg];
            Xs[ic][dy][xx] = v;
        }
        for (int i = t; i < 4608; i += 256) {
            int oc = i / 72, rem = i - oc * 72;
            int icl = rem / 9, tap = rem - icl * 9;
            Wsm[icl][tap][oc] = Wc[(size_t)(zh * 64 + oc) * 2304 + (ic0 + icl) * 9 + tap];
        }
        __syncthreads();
        #pragma unroll
        for (int ic = 0; ic < 8; ic++)
            #pragma unroll
            for (int tap = 0; tap < 9; tap++) {
                const int dy = tap / 3, dx = tap - dy * 3;
                float w[4], xv[4];
                #pragma unroll
                for (int o = 0; o < 4; o++) w[o] = Wsm[ic][tap][ocg * 4 + o];
                #pragma unroll
                for (int p = 0; p < 4; p++) xv[p] = Xs[ic][dy][pxg * 4 + p + dx];
                #pragma unroll
                for (int o = 0; o < 4; o++)
                    #pragma unroll
                    for (int p = 0; p < 4; p++) acc[o][p] += w[o] * xv[p];
            }
        __syncthreads();
    }
    #pragma unroll
    for (int o = 0; o < 4; o++) {
        int oc = zh * 64 + ocg * 4 + o;
        float inv = bng[oc] * rsqrtf(bnv[oc] + EPSV);
        float off = bnb[oc] - bnm[oc] * inv;
        #pragma unroll
        for (int p = 0; p < 4; p++) {
            int px = pxg * 4 + p;
            outp[((size_t)b * CI + oc) * NPIX + y * 64 + px] = fmaxf(acc[o][p] * inv + off, 0.f);
        }
    }
}

// ---------------- launch ----------------
extern "C" void kernel_launch(void* const* d_in, const int* in_sizes, int n_in,
                              void* d_out, int out_size)
{
    (void)in_sizes; (void)n_in; (void)out_size;
    const float* q     = (const float*)d_in[0];
    const float* s     = (const float*)d_in[1];
    const float* scale = (const float*)d_in[2];
    const float* w_v   = (const float*)d_in[3];  const float* b_v  = (const float*)d_in[4];
    const float* w_k1  = (const float*)d_in[5];  const float* b_k1 = (const float*)d_in[6];
    const float* w_q1  = (const float*)d_in[7];  const float* b_q1 = (const float*)d_in[8];
    const float* w_k2  = (const float*)d_in[9];  const float* b_k2 = (const float*)d_in[10];
    const float* w_q2  = (const float*)d_in[11]; const float* b_q2 = (const float*)d_in[12];
    const float* w_ts  = (const float*)d_in[13]; const float* b_ts = (const float*)d_in[14];
    const float* gts   = (const float*)d_in[15]; const float* bets = (const float*)d_in[16];
    const float* mts   = (const float*)d_in[17]; const float* vts  = (const float*)d_in[18];
    const float* w_tq  = (const float*)d_in[19]; const float* b_tq = (const float*)d_in[20];
    const float* gtq   = (const float*)d_in[21]; const float* betq = (const float*)d_in[22];
    const float* mtq   = (const float*)d_in[23]; const float* vtq  = (const float*)d_in[24];
    const float* w_cat = (const float*)d_in[25];
    const float* gcat  = (const float*)d_in[26]; const float* becat= (const float*)d_in[27];
    const float* mcat  = (const float*)d_in[28]; const float* vcat = (const float*)d_in[29];

    float* out  = (float*)d_out;
    float* cpam = out;
    float* Eq   = out + (size_t)NB * CI * NPIX;
    float* Es   = out + 2 * (size_t)NB * CI * NPIX;

    static bool attr_done = false;
    if (!attr_done) {
        cudaFuncSetAttribute(gemmA_mma, cudaFuncAttributeMaxDynamicSharedMemorySize, SMEMSZ);
        cudaFuncSetAttribute(pv_mma,   cudaFuncAttributeMaxDynamicSharedMemorySize, SMEMSZ);
        attr_done = true;
    }

    zero_sums<<<(NB * NPIX + 255) / 256, 256>>>();
    convs_kernel<<<dim3(32, NB, 12), 256>>>(q, s, w_v, b_v, w_k1, b_k1, w_q1, b_q1,
                                            w_k2, b_k2, w_q2, b_q2, w_ts, b_ts,
                                            gts, bets, mts, vts, w_tq, b_tq,
                                            gtq, betq, mtq, vtq);
    gemmA_mma<<<dim3(32, 32, NB), 256, SMEMSZ>>>();
    pv_mma<<<dim3(32, NB, 2), 256, SMEMSZ>>>(scale, Eq, Es);
    conv3x3_kernel<<<dim3(64, NB, 2), 256>>>(w_cat, gcat, becat, mcat, vcat, Eq, Es, cpam);
}